// round 16
// baseline (speedup 1.0000x reference)
#include <cuda_runtime.h>
#include <cuda_fp16.h>
#include <math.h>
#include <stdint.h>

#define BATCH  2
#define SEQ    1024
#define DMODEL 1024
#define DINNER 2048
#define DSTATE 16
#define NROWS  (BATCH*SEQ)      // 2048
#define DBCN   96
#define XZN    (2*DINNER)       // 4096
#define NSPLIT 8
#define NCHUNK 8
#define CHLEN  (SEQ/NCHUNK)     // 128

// ---------------- scratch (fp32) -------------------------------------------
__device__ float g_xz  [2][(size_t)NROWS*XZN];
__device__ float g_dbc [2][(size_t)NROWS*DBCN];
__device__ float g_dbcp[2][NSPLIT][(size_t)NROWS*DBCN];
__device__ float g_dt  [2][(size_t)NROWS*DINNER];
__device__ float g_outd[2][(size_t)NROWS*DMODEL];
__device__ float g_A   [2][DINNER*DSTATE];
__device__ int   g_fastA[2];
__device__ float g_hloc[2][BATCH][NCHUNK][DSTATE][DINNER];
__device__ float g_sdt [2][BATCH][NCHUNK][DINNER];

// ---------------- scratch (fp16 GEMM operands) ------------------------------
__device__ __half g_xh    [(size_t)NROWS*DMODEL];
__device__ __half g_winh  [2][(size_t)XZN*DMODEL];
__device__ __half g_xih   [2][(size_t)NROWS*DINNER];
__device__ __half g_xprojh[2][(size_t)DBCN*DINNER];
__device__ __half g_dbch  [2][(size_t)NROWS*DBCN];
__device__ __half g_dtwh  [2][(size_t)DINNER*64];
__device__ __half g_yh    [2][(size_t)NROWS*DINNER];
__device__ __half g_wouth [2][(size_t)DMODEL*DINNER];

// ---------------- helpers ---------------------------------------------------
__device__ __forceinline__ uint32_t smem_u32(const void* p) {
    uint32_t a;
    asm("{ .reg .u64 t; cvta.to.shared.u64 t, %1; cvt.u32.u64 %0, t; }"
        : "=r"(a) : "l"(p));
    return a;
}
__device__ __forceinline__ void cp16(uint32_t dst, const void* src, int sz) {
    asm volatile("cp.async.cg.shared.global [%0], [%1], 16, %2;"
                 :: "r"(dst), "l"(src), "r"(sz) : "memory");
}
__device__ __forceinline__ void cp_commit() {
    asm volatile("cp.async.commit_group;" ::: "memory");
}
__device__ __forceinline__ void cp_wait1() {
    asm volatile("cp.async.wait_group 1;" ::: "memory");
}
#define LDSM4(r0,r1,r2,r3,a) \
    asm volatile("ldmatrix.sync.aligned.m8n8.x4.shared.b16 {%0,%1,%2,%3}, [%4];" \
                 : "=r"(r0),"=r"(r1),"=r"(r2),"=r"(r3) : "r"(a))

// ---------------- fused fp32->fp16 conversion (9 segments, 1 launch) --------
struct CvtSegs {
    const float* s[9];
    __half*      d[9];
    int          off[10];
};
__global__ void f2h_multi_kernel(CvtSegs segs) {
    int i4 = (blockIdx.x*blockDim.x + threadIdx.x) * 4;
    if (i4 >= segs.off[9]) return;
    int j = 0;
    #pragma unroll
    for (int k = 1; k < 9; k++) j += (i4 >= segs.off[k]);
    int local = i4 - segs.off[j];
    float4 v = *(const float4*)(segs.s[j] + local);
    __half* dst = segs.d[j] + local;
    *(__half2*)(dst)   = __floats2half2_rn(v.x, v.y);
    *(__half2*)(dst+2) = __floats2half2_rn(v.z, v.w);
}

__global__ void prepA_kernel(const float* __restrict__ Alog0,
                             const float* __restrict__ Alog1) {
    int dir = blockIdx.x;
    const float* Alog = dir ? Alog1 : Alog0;
    __shared__ int ok;
    if (threadIdx.x == 0) ok = 1;
    __syncthreads();
    bool good = true;
    for (int i = threadIdx.x; i < DINNER*DSTATE; i += blockDim.x) {
        float a = -__expf(Alog[i]);
        g_A[dir][i] = a;
        int s = i & (DSTATE-1);
        if (fabsf(a + (float)(s+1)) > 1e-3f * (float)(s+1)) good = false;
    }
    if (!good) atomicExch(&ok, 0);
    __syncthreads();
    if (threadIdx.x == 0) g_fastA[dir] = ok;
}

// ==============  FP16 mma.sync GEMM (m16n8k16) — frozen internals ===========
#define HSTG 32768

template<int EPI>
__global__ __launch_bounds__(256, 2)
void hgemm(const __half* __restrict__ A0, const __half* __restrict__ A1,
           const __half* __restrict__ W0, const __half* __restrict__ W1,
           const float* __restrict__ b0, const float* __restrict__ b1,
           float* __restrict__ C0, float* __restrict__ C1,
           int N, int Ntot, int Ksub, int lda, int ldw,
           size_t csplit, int revA, int dirsel) {
    const int dir   = dirsel;
    const int split = blockIdx.z;
    const __half* A = dir ? A1 : A0;
    const __half* W = dir ? W1 : W0;
    const float* bias = dir ? b1 : b0;
    float* C = (dir ? C1 : C0) + (size_t)split * csplit;
    const int koff = split * Ksub;
    const int rev  = revA && dir;

    extern __shared__ __align__(16) char sm[];
    const uint32_t sbase = smem_u32(sm);

    const int tid  = threadIdx.x;
    const int lane = tid & 31;
    const int wid  = tid >> 5;
    const int warp_m = (wid & 1) * 64;
    const int warp_n = (wid >> 1) * 32;
    const int m0 = blockIdx.y * 128;
    const int n0 = blockIdx.x * 128;

    const int lrow = tid >> 2;
    const int lkc  = tid & 3;

    uint32_t aaddr[4], baddr[2];
    {
        int ar = warp_m + (lane & 7) + ((lane >> 3) & 1) * 8;
        int acb = (lane >> 4) & 1;
        #pragma unroll
        for (int mi = 0; mi < 4; mi++) {
            int r = ar + mi*16;
            aaddr[mi] = r*64 + ((acb ^ ((r>>1)&3))*16);
        }
        int br = warp_n + (lane & 7) + ((lane >> 4) & 1) * 8;
        int bcb = (lane >> 3) & 1;
        #pragma unroll
        for (int p = 0; p < 2; p++) {
            int r = br + p*16;
            baddr[p] = r*64 + ((bcb ^ ((r>>1)&3))*16);
        }
    }

    float acc[4][4][4];
    #pragma unroll
    for (int i = 0; i < 4; i++)
        #pragma unroll
        for (int j = 0; j < 4; j++)
            #pragma unroll
            for (int r = 0; r < 4; r++) acc[i][j][r] = 0.f;

    const int nk = Ksub / 64;

    auto stage_load = [&](int it) {
        uint32_t sA = sbase + (it % 3)*HSTG;
        uint32_t sB = sA + 16384;
        int k0 = koff + it*64;
        #pragma unroll
        for (int kh = 0; kh < 2; kh++) {
            int kk = k0 + kh*32;
            #pragma unroll
            for (int j = 0; j < 2; j++) {
                int row = lrow + j*64;
                int gm = m0 + row;
                if (rev) gm = (gm & ~(SEQ-1)) | ((SEQ-1) - (gm & (SEQ-1)));
                uint32_t d = sA + kh*8192 + row*64 + ((lkc ^ ((row>>1)&3))*16);
                cp16(d, A + (size_t)gm*lda + kk + lkc*8, 16);
            }
            #pragma unroll
            for (int j = 0; j < 2; j++) {
                int row = lrow + j*64;
                int wr = n0 + row;
                int valid = (wr < N);
                uint32_t d = sB + kh*8192 + row*64 + ((lkc ^ ((row>>1)&3))*16);
                cp16(d, W + (size_t)(valid ? wr : 0)*ldw + kk + lkc*8, valid ? 16 : 0);
            }
        }
        cp_commit();
    };

    stage_load(0);
    if (nk > 1) stage_load(1); else cp_commit();

    for (int it = 0; it < nk; it++) {
        cp_wait1();
        __syncthreads();
        if (it + 2 < nk) stage_load(it + 2); else cp_commit();

        uint32_t sb = sbase + (it % 3)*HSTG;
        #pragma unroll
        for (int ks4 = 0; ks4 < 4; ks4++) {
            const uint32_t sub = (uint32_t)(ks4 >> 1) * 8192;
            const uint32_t kx  = (uint32_t)(ks4 & 1) * 32;
            uint32_t af[4][4];
            #pragma unroll
            for (int mi = 0; mi < 4; mi++)
                LDSM4(af[mi][0], af[mi][1], af[mi][2], af[mi][3],
                      sb + sub + (aaddr[mi] ^ kx));
            uint32_t bf[4][2];
            #pragma unroll
            for (int p = 0; p < 2; p++)
                LDSM4(bf[2*p][0], bf[2*p][1], bf[2*p+1][0], bf[2*p+1][1],
                      sb + 16384 + sub + (baddr[p] ^ kx));
            #pragma unroll
            for (int mi = 0; mi < 4; mi++)
                #pragma unroll
                for (int ni = 0; ni < 4; ni++) {
                    asm volatile(
                        "mma.sync.aligned.m16n8k16.row.col.f32.f16.f16.f32 "
                        "{%0,%1,%2,%3}, {%4,%5,%6,%7}, {%8,%9}, {%0,%1,%2,%3};"
                        : "+f"(acc[mi][ni][0]), "+f"(acc[mi][ni][1]),
                          "+f"(acc[mi][ni][2]), "+f"(acc[mi][ni][3])
                        : "r"(af[mi][0]), "r"(af[mi][1]),
                          "r"(af[mi][2]), "r"(af[mi][3]),
                          "r"(bf[ni][0]), "r"(bf[ni][1]));
                }
        }
        __syncthreads();
    }

    #pragma unroll
    for (int mi = 0; mi < 4; mi++) {
        #pragma unroll
        for (int ni = 0; ni < 4; ni++) {
            int row = m0 + warp_m + mi*16 + (lane>>2);
            int col = n0 + warp_n + ni*8 + 2*(lane&3);
            #pragma unroll
            for (int half = 0; half < 2; half++) {
                int r = row + half*8;
                float v0 = acc[mi][ni][half*2+0];
                float v1 = acc[mi][ni][half*2+1];
                if (EPI == 1) {
                    v0 += bias[col];   v1 += bias[col+1];
                    v0 = (v0 > 20.f) ? v0 : log1pf(__expf(v0));
                    v1 = (v1 > 20.f) ? v1 : log1pf(__expf(v1));
                } else if (EPI == 2) {
                    v0 = 1.f / (1.f + __expf(-v0));
                    v1 = 1.f / (1.f + __expf(-v1));
                }
                if (col + 1 < N)
                    *(float2*)(C + (size_t)r*Ntot + col) = make_float2(v0, v1);
            }
        }
    }
}

// ---------------- split-K reduce for x_proj (per-dir) ------------------------
__global__ void reduce_dbc_kernel(int dirsel) {
    int idx = blockIdx.x * blockDim.x + threadIdx.x;
    const int TOT = NROWS*DBCN;
    if (idx >= TOT) return;
    int dir = dirsel;
    float s = 0.f;
    #pragma unroll
    for (int p = 0; p < NSPLIT; p++) s += g_dbcp[dir][p][idx];
    g_dbc[dir][idx] = s;
    g_dbch[dir][idx] = __float2half(s);
}

// ---------------- causal depthwise conv (k=4) + SiLU -> fp16 (per-dir) ------
__global__ void conv_silu_kernel(const float* __restrict__ w0, const float* __restrict__ w1,
                                 const float* __restrict__ cb0, const float* __restrict__ cb1,
                                 int dirsel) {
    int dir = dirsel;
    const float* w  = dir ? w1 : w0;
    const float* cb = dir ? cb1 : cb0;
    int idx = blockIdx.x * blockDim.x + threadIdx.x;
    const int NC4 = DINNER/4;
    const int NPAIR = NROWS/2;
    if (idx >= NPAIR * NC4) return;
    int c4 = idx % NC4;
    int pr = idx / NC4;
    int row0 = pr * 2;
    int l0 = row0 & (SEQ-1);
    const float* base = g_xz[dir] + (size_t)row0*XZN + c4*4;
    float4 xp1 = *(const float4*)(base + XZN);
    float4 x0  = *(const float4*)(base);
    float4 xm1 = (l0>=1) ? *(const float4*)(base - 1*XZN) : make_float4(0,0,0,0);
    float4 xm2 = (l0>=2) ? *(const float4*)(base - 2*XZN) : make_float4(0,0,0,0);
    float4 xm3 = (l0>=3) ? *(const float4*)(base - 3*XZN) : make_float4(0,0,0,0);
    float4 cbv = ((const float4*)cb)[c4];

    float o0[4], o1[4];
    const float* cbp = (const float*)&cbv;
    const float* pxp1 = (const float*)&xp1;
    const float* px0  = (const float*)&x0;
    const float* pxm1 = (const float*)&xm1;
    const float* pxm2 = (const float*)&xm2;
    const float* pxm3 = (const float*)&xm3;
    #pragma unroll
    for (int c = 0; c < 4; c++) {
        float4 wv = ((const float4*)w)[c4*4+c];
        float a = cbp[c];
        a = fmaf(wv.x, pxm3[c], a);
        a = fmaf(wv.y, pxm2[c], a);
        a = fmaf(wv.z, pxm1[c], a);
        a = fmaf(wv.w, px0[c], a);
        o0[c] = a / (1.f + __expf(-a));
        float b = cbp[c];
        b = fmaf(wv.x, pxm2[c], b);
        b = fmaf(wv.y, pxm1[c], b);
        b = fmaf(wv.z, px0[c], b);
        b = fmaf(wv.w, pxp1[c], b);
        o1[c] = b / (1.f + __expf(-b));
    }
    __half* h0 = g_xih[dir] + (size_t)row0*DINNER + c4*4;
    *(__half2*)(h0)            = __floats2half2_rn(o0[0], o0[1]);
    *(__half2*)(h0+2)          = __floats2half2_rn(o0[2], o0[3]);
    *(__half2*)(h0+DINNER)     = __floats2half2_rn(o1[0], o1[1]);
    *(__half2*)(h0+DINNER+2)   = __floats2half2_rn(o1[2], o1[3]);
}

// ---------------- chunked scan: pass A (per-dir) -----------------------------
__global__ __launch_bounds__(128)
void scan_local_kernel(const float* __restrict__ cw0, const float* __restrict__ cw1,
                       const float* __restrict__ cb0, const float* __restrict__ cb1,
                       int dirsel) {
    int dir = dirsel;
    int b   = blockIdx.z;
    int c   = blockIdx.y;                 // 0..NCHUNK-2
    int d   = blockIdx.x * 128 + threadIdx.x;
    int row0 = c * CHLEN;

    __shared__ float4 sB[CHLEN][4];
    for (int i = threadIdx.x; i < CHLEN*4; i += 128) {
        int row = i >> 2, q = i & 3;
        sB[row][q] = *(const float4*)(g_dbc[dir] +
                        (size_t)(b*SEQ + row0 + row)*DBCN + 64 + q*4);
    }
    __syncthreads();

    const float* dtp = g_dt[dir]  + ((size_t)(b*SEQ + row0))*DINNER + d;
    const float* xzp = g_xz[dir]  + ((size_t)(b*SEQ + row0))*XZN + d;
    const float* cw  = dir ? cw1 : cw0;
    const float* cb  = dir ? cb1 : cb0;

    float4 wv = ((const float4*)cw)[d];
    float cbv = cb[d];
    float x1 = 0.f, x2 = 0.f, x3 = 0.f;
    if (c > 0) {
        x1 = xzp[-(ptrdiff_t)XZN];
        x2 = xzp[-(ptrdiff_t)(2*XZN)];
        x3 = xzp[-(ptrdiff_t)(3*XZN)];
    }

    float h[DSTATE];
    #pragma unroll
    for (int s = 0; s < DSTATE; s++) h[s] = 0.f;
    float Av[DSTATE];
    #pragma unroll
    for (int s = 0; s < DSTATE; s++) Av[s] = g_A[dir][d*DSTATE + s];
    int fast = g_fastA[dir];
    float sdt = 0.f;

    #pragma unroll 1
    for (int l0 = 0; l0 < CHLEN; l0 += 4) {
        float cdt[4], cx[4];
        #pragma unroll
        for (int u = 0; u < 4; u++) {
            int r = l0 + u;
            cdt[u] = dtp[(size_t)r*DINNER];
            cx[u]  = xzp[(size_t)r*XZN];
        }
        #pragma unroll
        for (int u = 0; u < 4; u++) {
            int r = l0 + u;
            float dt = cdt[u], xc = cx[u];
            float a = cbv;
            a = fmaf(wv.x, x3, a);
            a = fmaf(wv.y, x2, a);
            a = fmaf(wv.z, x1, a);
            a = fmaf(wv.w, xc, a);
            float xi = a / (1.f + __expf(-a));
            x3 = x2; x2 = x1; x1 = xc;

            float4 b0 = sB[r][0], b1 = sB[r][1], b2 = sB[r][2], b3 = sB[r][3];
            float bsv[16] = {b0.x,b0.y,b0.z,b0.w, b1.x,b1.y,b1.z,b1.w,
                             b2.x,b2.y,b2.z,b2.w, b3.x,b3.y,b3.z,b3.w};
            float dtxi = dt * xi;
            sdt += dt;
            if (fast) {
                float e = __expf(-dt);
                float p = 1.f;
                #pragma unroll
                for (int s = 0; s < DSTATE; s++) {
                    p *= e;
                    h[s] = fmaf(p, h[s], dtxi * bsv[s]);
                }
            } else {
                #pragma unroll
                for (int s = 0; s < DSTATE; s++) {
                    float aa = __expf(dt * Av[s]);
                    h[s] = fmaf(aa, h[s], dtxi * bsv[s]);
                }
            }
        }
    }
    #pragma unroll
    for (int s = 0; s < DSTATE; s++) g_hloc[dir][b][c][s][d] = h[s];
    g_sdt[dir][b][c][d] = sdt;
}

// ---------------- chunked scan: pass C (per-dir) -----------------------------
__global__ __launch_bounds__(128)
void scan_final_kernel(const float* __restrict__ cw0, const float* __restrict__ cw1,
                       const float* __restrict__ cb0, const float* __restrict__ cb1,
                       const float* __restrict__ D0, const float* __restrict__ D1,
                       int dirsel) {
    int dir = dirsel;
    int b   = blockIdx.z;
    int c   = blockIdx.y;
    int d   = blockIdx.x * 128 + threadIdx.x;
    int row0 = c * CHLEN;
    const float* Dp = dir ? D1 : D0;

    __shared__ float4 sBC[CHLEN][8];
    for (int i = threadIdx.x; i < CHLEN*8; i += 128) {
        int row = i >> 3, q = i & 7;
        sBC[row][q] = *(const float4*)(g_dbc[dir] +
                         (size_t)(b*SEQ + row0 + row)*DBCN + 64 + q*4);
    }
    __syncthreads();

    const float* dtp = g_dt[dir]  + ((size_t)(b*SEQ + row0))*DINNER + d;
    const float* xzp = g_xz[dir]  + ((size_t)(b*SEQ + row0))*XZN + d;
    const float* zp  = g_xz[dir]  + ((size_t)(b*SEQ + row0))*XZN + DINNER + d;
    __half* yp       = g_yh[dir]  + ((size_t)(b*SEQ + row0))*DINNER + d;
    const float* cw  = dir ? cw1 : cw0;
    const float* cb  = dir ? cb1 : cb0;

    float Av[DSTATE];
    #pragma unroll
    for (int s = 0; s < DSTATE; s++) Av[s] = g_A[dir][d*DSTATE + s];
    int fast = g_fastA[dir];

    float h[DSTATE];
    #pragma unroll
    for (int s = 0; s < DSTATE; s++) h[s] = 0.f;
    for (int cc = 0; cc < c; cc++) {
        float S = g_sdt[dir][b][cc][d];
        if (fast) {
            float E = __expf(-S);
            float p = 1.f;
            #pragma unroll
            for (int s = 0; s < DSTATE; s++) {
                p *= E;
                h[s] = fmaf(p, h[s], g_hloc[dir][b][cc][s][d]);
            }
        } else {
            #pragma unroll
            for (int s = 0; s < DSTATE; s++) {
                float aa = __expf(Av[s] * S);
                h[s] = fmaf(aa, h[s], g_hloc[dir][b][cc][s][d]);
            }
        }
    }

    float4 wv = ((const float4*)cw)[d];
    float cbv = cb[d];
    float x1 = 0.f, x2 = 0.f, x3 = 0.f;
    if (c > 0) {
        x1 = xzp[-(ptrdiff_t)XZN];
        x2 = xzp[-(ptrdiff_t)(2*XZN)];
        x3 = xzp[-(ptrdiff_t)(3*XZN)];
    }
    float Dv = Dp[d];

    #pragma unroll 1
    for (int l0 = 0; l0 < CHLEN; l0 += 4) {
        float cdt[4], cx[4], cz[4];
        #pragma unroll
        for (int u = 0; u < 4; u++) {
            int r = l0 + u;
            cdt[u] = dtp[(size_t)r*DINNER];
            cx[u]  = xzp[(size_t)r*XZN];
            cz[u]  = zp [(size_t)r*XZN];
        }
        #pragma unroll
        for (int u = 0; u < 4; u++) {
            int r = l0 + u;
            float dt = cdt[u], xc = cx[u], z = cz[u];
            float a = cbv;
            a = fmaf(wv.x, x3, a);
            a = fmaf(wv.y, x2, a);
            a = fmaf(wv.z, x1, a);
            a = fmaf(wv.w, xc, a);
            float xi = a / (1.f + __expf(-a));
            x3 = x2; x2 = x1; x1 = xc;

            float4 b0 = sBC[r][0], b1 = sBC[r][1], b2 = sBC[r][2], b3 = sBC[r][3];
            float4 c0 = sBC[r][4], c1 = sBC[r][5], c2 = sBC[r][6], c3 = sBC[r][7];
            float bsv[16] = {b0.x,b0.y,b0.z,b0.w, b1.x,b1.y,b1.z,b1.w,
                             b2.x,b2.y,b2.z,b2.w, b3.x,b3.y,b3.z,b3.w};
            float csv[16] = {c0.x,c0.y,c0.z,c0.w, c1.x,c1.y,c1.z,c1.w,
                             c2.x,c2.y,c2.z,c2.w, c3.x,c3.y,c3.z,c3.w};

            float dtxi = dt * xi;
            float acc = 0.f;
            if (fast) {
                float e = __expf(-dt);
                float p = 1.f;
                #pragma unroll
                for (int s = 0; s < DSTATE; s++) {
                    p *= e;
                    h[s] = fmaf(p, h[s], dtxi * bsv[s]);
                    acc = fmaf(h[s], csv[s], acc);
                }
            } else {
                #pragma unroll
                for (int s = 0; s < DSTATE; s++) {
                    float aa = __expf(dt * Av[s]);
                    h[s] = fmaf(aa, h[s], dtxi * bsv[s]);
                    acc = fmaf(h[s], csv[s], acc);
                }
            }
            float sz = z / (1.f + __expf(-z));
            yp[(size_t)r*DINNER] = __float2half((acc + xi * Dv) * sz);
        }
    }
}

// ---------------- combine dirs + LayerNorm + residual (float4) --------------
__global__ __launch_bounds__(256)
void combine_ln_kernel(const float* __restrict__ x,
                       const float* __restrict__ lng, const float* __restrict__ lnb,
                       float* __restrict__ out) {
    int row = blockIdx.x;
    int b = row / SEQ, l = row % SEQ;
    const float* f  = g_outd[0] + (size_t)row*DMODEL;
    const float* bk = g_outd[1] + (size_t)(b*SEQ + (SEQ-1-l))*DMODEL;
    int tid = threadIdx.x;

    float4 fv = *(const float4*)(f + tid*4);
    float4 bv = *(const float4*)(bk + tid*4);
    float4 dv = make_float4(0.5f*(fv.x+bv.x), 0.5f*(fv.y+bv.y),
                            0.5f*(fv.z+bv.z), 0.5f*(fv.w+bv.w));
    float s  = dv.x + dv.y + dv.z + dv.w;
    float s2 = dv.x*dv.x + dv.y*dv.y + dv.z*dv.z + dv.w*dv.w;
    #pragma unroll
    for (int o = 16; o; o >>= 1) {
        s  += __shfl_xor_sync(0xffffffffu, s,  o);
        s2 += __shfl_xor_sync(0xffffffffu, s2, o);
    }
    __shared__ float sh[2][8];
    if ((tid & 31) == 0) { sh[0][tid>>5] = s; sh[1][tid>>5] = s2; }
    __syncthreads();
    if (tid < 32) {
        float a  = (tid < 8) ? sh[0][tid] : 0.f;
        float a2 = (tid < 8) ? sh[1][tid] : 0.f;
        #pragma unroll
        for (int o = 4; o; o >>= 1) {
            a  += __shfl_xor_sync(0xffffffffu, a,  o);
            a2 += __shfl_xor_sync(0xffffffffu, a2, o);
        }
        if (tid == 0) { sh[0][0] = a; sh[1][0] = a2; }
    }
    __syncthreads();
    float mu  = sh[0][0] * (1.f/DMODEL);
    float var = sh[1][0] * (1.f/DMODEL) - mu*mu;
    float rstd = rsqrtf(var + 1e-5f);
    float4 gv = *(const float4*)(lng + tid*4);
    float4 bb = *(const float4*)(lnb + tid*4);
    float4 xv = *(const float4*)(x + (size_t)row*DMODEL + tid*4);
    float4 ov;
    ov.x = (dv.x - mu)*rstd*gv.x + bb.x + xv.x;
    ov.y = (dv.y - mu)*rstd*gv.y + bb.y + xv.y;
    ov.z = (dv.z - mu)*rstd*gv.z + bb.z + xv.z;
    ov.w = (dv.w - mu)*rstd*gv.w + bb.w + xv.w;
    *(float4*)(out + (size_t)row*DMODEL + tid*4) = ov;
}

// ---------------- host launcher --------------------------------------------
extern "C" void kernel_launch(void* const* d_in, const int* in_sizes, int n_in,
                              void* d_out, int out_size) {
    (void)in_sizes; (void)n_in; (void)out_size;
    const float* x       = (const float*)d_in[0];
    const float* Win[2]  = {(const float*)d_in[1],  (const float*)d_in[10]};
    const float* cw[2]   = {(const float*)d_in[2],  (const float*)d_in[11]};
    const float* cbv[2]  = {(const float*)d_in[3],  (const float*)d_in[12]};
    const float* xproj[2]= {(const float*)d_in[4],  (const float*)d_in[13]};
    const float* dtw[2]  = {(const float*)d_in[5],  (const float*)d_in[14]};
    const float* dtb[2]  = {(const float*)d_in[6],  (const float*)d_in[15]};
    const float* Alog[2] = {(const float*)d_in[7],  (const float*)d_in[16]};
    const float* Dp[2]   = {(const float*)d_in[8],  (const float*)d_in[17]};
    const float* Wout[2] = {(const float*)d_in[9],  (const float*)d_in[18]};
    const float* lng = (const float*)d_in[19];
    const float* lnb = (const float*)d_in[20];
    float* out = (float*)d_out;

    float *p_xz, *p_dbcp, *p_dt, *p_out;
    cudaGetSymbolAddress((void**)&p_xz,   g_xz);
    cudaGetSymbolAddress((void**)&p_dbcp, g_dbcp);
    cudaGetSymbolAddress((void**)&p_dt,   g_dt);
    cudaGetSymbolAddress((void**)&p_out,  g_outd);
    __half *p_xh, *p_winh, *p_xih, *p_xprojh, *p_dbch, *p_dtwh, *p_yh, *p_wouth;
    cudaGetSymbolAddress((void**)&p_xh,     g_xh);
    cudaGetSymbolAddress((void**)&p_winh,   g_winh);
    cudaGetSymbolAddress((void**)&p_xih,    g_xih);
    cudaGetSymbolAddress((void**)&p_xprojh, g_xprojh);
    cudaGetSymbolAddress((void**)&p_dbch,   g_dbch);
    cudaGetSymbolAddress((void**)&p_dtwh,   g_dtwh);
    cudaGetSymbolAddress((void**)&p_yh,     g_yh);
    cudaGetSymbolAddress((void**)&p_wouth,  g_wouth);

    const size_t sXZ  = (size_t)NROWS*XZN;
    const size_t sIN  = (size_t)NROWS*DINNER;
    const size_t sDBC = (size_t)NROWS*DBCN;
    const size_t sMD  = (size_t)NROWS*DMODEL;
    const int SMEM = 3*HSTG;   // 98304

    cudaFuncSetAttribute(hgemm<0>, cudaFuncAttributeMaxDynamicSharedMemorySize, SMEM);
    cudaFuncSetAttribute(hgemm<1>, cudaFuncAttributeMaxDynamicSharedMemorySize, SMEM);
    cudaFuncSetAttribute(hgemm<2>, cudaFuncAttributeMaxDynamicSharedMemorySize, SMEM);

    cudaStream_t s1;
    cudaEvent_t evMid, evJ;
    cudaStreamCreateWithFlags(&s1, cudaStreamNonBlocking);
    cudaEventCreateWithFlags(&evMid, cudaEventDisableTiming);
    cudaEventCreateWithFlags(&evJ, cudaEventDisableTiming);

    prepA_kernel<<<2, 256>>>(Alog[0], Alog[1]);

    {
        CvtSegs cs;
        const float* srcs[9] = {x, Win[0], Win[1], xproj[0], xproj[1],
                                dtw[0], dtw[1], Wout[0], Wout[1]};
        __half* dsts[9] = {p_xh, p_winh, p_winh + (size_t)XZN*DMODEL,
                           p_xprojh, p_xprojh + (size_t)DBCN*DINNER,
                           p_dtwh, p_dtwh + (size_t)DINNER*64,
                           p_wouth, p_wouth + (size_t)DMODEL*DINNER};
        int cnts[9] = {NROWS*DMODEL, XZN*DMODEL, XZN*DMODEL,
                       DBCN*DINNER, DBCN*DINNER, DINNER*64, DINNER*64,
                       DMODEL*DINNER, DMODEL*DINNER};
        int off = 0;
        for (int i = 0; i < 9; i++) { cs.s[i]=srcs[i]; cs.d[i]=dsts[i]; cs.off[i]=off; off+=cnts[i]; }
        cs.off[9] = off;
        f2h_multi_kernel<<<(off/4 + 255)/256, 256>>>(cs);
    }

    // dir0: in_proj on stream 0
    hgemm<0><<<dim3(XZN/128, NROWS/128, 1), 256, SMEM>>>(
        p_xh, p_xh, p_winh, p_winh + (size_t)XZN*DMODEL, nullptr, nullptr,
        p_xz, p_xz + sXZ, XZN, XZN, DMODEL, DMODEL, DMODEL, 0, 1, 0);

    // skewed fork: dir1 chain starts only after dir0's in_proj completes
    cudaEventRecord(evMid, 0);
    cudaStreamWaitEvent(s1, evMid, 0);

    // dir1 full chain on s1 (phase-offset from dir0)
    {
        const int dir = 1;
        hgemm<0><<<dim3(XZN/128, NROWS/128, 1), 256, SMEM, s1>>>(
            p_xh, p_xh, p_winh, p_winh + (size_t)XZN*DMODEL, nullptr, nullptr,
            p_xz, p_xz + sXZ, XZN, XZN, DMODEL, DMODEL, DMODEL, 0, 1, dir);
        conv_silu_kernel<<<dim3(((NROWS/2)*(DINNER/4) + 255)/256, 1, 1), 256, 0, s1>>>(
            cw[0], cw[1], cbv[0], cbv[1], dir);
        hgemm<0><<<dim3(1, NROWS/128, NSPLIT), 256, SMEM, s1>>>(
            p_xih, p_xih + sIN, p_xprojh, p_xprojh + (size_t)DBCN*DINNER,
            nullptr, nullptr,
            p_dbcp, p_dbcp + NSPLIT*sDBC, DBCN, DBCN, DINNER/NSPLIT, DINNER, DINNER,
            sDBC, 0, dir);
        reduce_dbc_kernel<<<(NROWS*DBCN + 255)/256, 256, 0, s1>>>(dir);
        hgemm<1><<<dim3(DINNER/128, NROWS/128, 1), 256, SMEM, s1>>>(
            p_dbch, p_dbch + sDBC, p_dtwh, p_dtwh + (size_t)DINNER*64, dtb[0], dtb[1],
            p_dt, p_dt + sIN, DINNER, DINNER, 64, DBCN, 64, 0, 0, dir);
        scan_local_kernel<<<dim3(DINNER/128, NCHUNK-1, BATCH), 128, 0, s1>>>(
            cw[0], cw[1], cbv[0], cbv[1], dir);
        scan_final_kernel<<<dim3(DINNER/128, NCHUNK, BATCH), 128, 0, s1>>>(
            cw[0], cw[1], cbv[0], cbv[1], Dp[0], Dp[1], dir);
        hgemm<2><<<dim3(DMODEL/128, NROWS/128, 1), 256, SMEM, s1>>>(
            p_yh, p_yh + sIN, p_wouth, p_wouth + (size_t)DMODEL*DINNER,
            nullptr, nullptr,
            p_out, p_out + sMD, DMODEL, DMODEL, DINNER, DINNER, DINNER, 0, 0, dir);
    }

    // dir0 remainder on stream 0 (overlaps dir1's chain)
    {
        const int dir = 0;
        conv_silu_kernel<<<dim3(((NROWS/2)*(DINNER/4) + 255)/256, 1, 1), 256>>>(
            cw[0], cw[1], cbv[0], cbv[1], dir);
        hgemm<0><<<dim3(1, NROWS/128, NSPLIT), 256, SMEM>>>(
            p_xih, p_xih + sIN, p_xprojh, p_xprojh + (size_t)DBCN*DINNER,
            nullptr, nullptr,
            p_dbcp, p_dbcp + NSPLIT*sDBC, DBCN, DBCN, DINNER/NSPLIT, DINNER, DINNER,
            sDBC, 0, dir);
        reduce_dbc_kernel<<<(NROWS*DBCN + 255)/256, 256>>>(dir);
        hgemm<1><<<dim3(DINNER/128, NROWS/128, 1), 256, SMEM>>>(
            p_dbch, p_dbch + sDBC, p_dtwh, p_dtwh + (size_t)DINNER*64, dtb[0], dtb[1],
            p_dt, p_dt + sIN, DINNER, DINNER, 64, DBCN, 64, 0, 0, dir);
        scan_local_kernel<<<dim3(DINNER/128, NCHUNK-1, BATCH), 128>>>(
            cw[0], cw[1], cbv[0], cbv[1], dir);
        scan_final_kernel<<<dim3(DINNER/128, NCHUNK, BATCH), 128>>>(
            cw[0], cw[1], cbv[0], cbv[1], Dp[0], Dp[1], dir);
        hgemm<2><<<dim3(DMODEL/128, NROWS/128, 1), 256, SMEM>>>(
            p_yh, p_yh + sIN, p_wouth, p_wouth + (size_t)DMODEL*DINNER,
            nullptr, nullptr,
            p_out, p_out + sMD, DMODEL, DMODEL, DINNER, DINNER, DINNER, 0, 0, dir);
    }

    // join, then LN on stream 0
    cudaEventRecord(evJ, s1);
    cudaStreamWaitEvent((cudaStream_t)0, evJ, 0);
    combine_ln_kernel<<<NROWS, 256>>>(x, lng, lnb, out);
}

// round 17
// speedup vs baseline: 1.0524x; 1.0524x over previous
#include <cuda_runtime.h>
#include <cuda_fp16.h>
#include <math.h>
#include <stdint.h>

#define BATCH  2
#define SEQ    1024
#define DMODEL 1024
#define DINNER 2048
#define DSTATE 16
#define NROWS  (BATCH*SEQ)      // 2048
#define DBCN   96
#define XZN    (2*DINNER)       // 4096
#define NSPLIT 8
#define NCHUNK 8
#define CHLEN  (SEQ/NCHUNK)     // 128

// ---------------- scratch (fp32) -------------------------------------------
__device__ float g_xz  [2][(size_t)NROWS*XZN];
__device__ float g_dbc [2][(size_t)NROWS*DBCN];
__device__ float g_dbcp[2][NSPLIT][(size_t)NROWS*DBCN];
__device__ float g_dt  [2][(size_t)NROWS*DINNER];
__device__ float g_outd[2][(size_t)NROWS*DMODEL];
__device__ float g_A   [2][DINNER*DSTATE];
__device__ int   g_fastA[2];
__device__ float g_hloc[2][BATCH][NCHUNK][DSTATE][DINNER];
__device__ float g_sdt [2][BATCH][NCHUNK][DINNER];

// ---------------- scratch (fp16 GEMM operands) ------------------------------
__device__ __half g_xh    [(size_t)NROWS*DMODEL];
__device__ __half g_winh  [2][(size_t)XZN*DMODEL];
__device__ __half g_xih   [2][(size_t)NROWS*DINNER];
__device__ __half g_xprojh[2][(size_t)DBCN*DINNER];
__device__ __half g_dbch  [2][(size_t)NROWS*DBCN];
__device__ __half g_dtwh  [2][(size_t)DINNER*64];
__device__ __half g_yh    [2][(size_t)NROWS*DINNER];
__device__ __half g_wouth [2][(size_t)DMODEL*DINNER];

// ---------------- helpers ---------------------------------------------------
__device__ __forceinline__ uint32_t smem_u32(const void* p) {
    uint32_t a;
    asm("{ .reg .u64 t; cvta.to.shared.u64 t, %1; cvt.u32.u64 %0, t; }"
        : "=r"(a) : "l"(p));
    return a;
}
__device__ __forceinline__ void cp16(uint32_t dst, const void* src, int sz) {
    asm volatile("cp.async.cg.shared.global [%0], [%1], 16, %2;"
                 :: "r"(dst), "l"(src), "r"(sz) : "memory");
}
__device__ __forceinline__ void cp_commit() {
    asm volatile("cp.async.commit_group;" ::: "memory");
}
__device__ __forceinline__ void cp_wait1() {
    asm volatile("cp.async.wait_group 1;" ::: "memory");
}
#define LDSM4(r0,r1,r2,r3,a) \
    asm volatile("ldmatrix.sync.aligned.m8n8.x4.shared.b16 {%0,%1,%2,%3}, [%4];" \
                 : "=r"(r0),"=r"(r1),"=r"(r2),"=r"(r3) : "r"(a))

// ---------------- fused fp32->fp16 conversion (9 segments, 1 launch) --------
struct CvtSegs {
    const float* s[9];
    __half*      d[9];
    int          off[10];
};
__global__ void f2h_multi_kernel(CvtSegs segs) {
    int i4 = (blockIdx.x*blockDim.x + threadIdx.x) * 4;
    if (i4 >= segs.off[9]) return;
    int j = 0;
    #pragma unroll
    for (int k = 1; k < 9; k++) j += (i4 >= segs.off[k]);
    int local = i4 - segs.off[j];
    float4 v = *(const float4*)(segs.s[j] + local);
    __half* dst = segs.d[j] + local;
    *(__half2*)(dst)   = __floats2half2_rn(v.x, v.y);
    *(__half2*)(dst+2) = __floats2half2_rn(v.z, v.w);
}

__global__ void prepA_kernel(const float* __restrict__ Alog0,
                             const float* __restrict__ Alog1) {
    int dir = blockIdx.x;
    const float* Alog = dir ? Alog1 : Alog0;
    __shared__ int ok;
    if (threadIdx.x == 0) ok = 1;
    __syncthreads();
    bool good = true;
    for (int i = threadIdx.x; i < DINNER*DSTATE; i += blockDim.x) {
        float a = -__expf(Alog[i]);
        g_A[dir][i] = a;
        int s = i & (DSTATE-1);
        if (fabsf(a + (float)(s+1)) > 1e-3f * (float)(s+1)) good = false;
    }
    if (!good) atomicExch(&ok, 0);
    __syncthreads();
    if (threadIdx.x == 0) g_fastA[dir] = ok;
}

// ==============  FP16 mma.sync GEMM (m16n8k16) — frozen internals ===========
#define HSTG 32768

template<int EPI>
__global__ __launch_bounds__(256, 2)
void hgemm(const __half* __restrict__ A0, const __half* __restrict__ A1,
           const __half* __restrict__ W0, const __half* __restrict__ W1,
           const float* __restrict__ b0, const float* __restrict__ b1,
           float* __restrict__ C0, float* __restrict__ C1,
           int N, int Ntot, int Ksub, int lda, int ldw,
           size_t csplit, int revA, int dirsel) {
    const int dir   = dirsel;
    const int split = blockIdx.z;
    const __half* A = dir ? A1 : A0;
    const __half* W = dir ? W1 : W0;
    const float* bias = dir ? b1 : b0;
    float* C = (dir ? C1 : C0) + (size_t)split * csplit;
    const int koff = split * Ksub;
    const int rev  = revA && dir;

    extern __shared__ __align__(16) char sm[];
    const uint32_t sbase = smem_u32(sm);

    const int tid  = threadIdx.x;
    const int lane = tid & 31;
    const int wid  = tid >> 5;
    const int warp_m = (wid & 1) * 64;
    const int warp_n = (wid >> 1) * 32;
    const int m0 = blockIdx.y * 128;
    const int n0 = blockIdx.x * 128;

    const int lrow = tid >> 2;
    const int lkc  = tid & 3;

    uint32_t aaddr[4], baddr[2];
    {
        int ar = warp_m + (lane & 7) + ((lane >> 3) & 1) * 8;
        int acb = (lane >> 4) & 1;
        #pragma unroll
        for (int mi = 0; mi < 4; mi++) {
            int r = ar + mi*16;
            aaddr[mi] = r*64 + ((acb ^ ((r>>1)&3))*16);
        }
        int br = warp_n + (lane & 7) + ((lane >> 4) & 1) * 8;
        int bcb = (lane >> 3) & 1;
        #pragma unroll
        for (int p = 0; p < 2; p++) {
            int r = br + p*16;
            baddr[p] = r*64 + ((bcb ^ ((r>>1)&3))*16);
        }
    }

    float acc[4][4][4];
    #pragma unroll
    for (int i = 0; i < 4; i++)
        #pragma unroll
        for (int j = 0; j < 4; j++)
            #pragma unroll
            for (int r = 0; r < 4; r++) acc[i][j][r] = 0.f;

    const int nk = Ksub / 64;

    auto stage_load = [&](int it) {
        uint32_t sA = sbase + (it % 3)*HSTG;
        uint32_t sB = sA + 16384;
        int k0 = koff + it*64;
        #pragma unroll
        for (int kh = 0; kh < 2; kh++) {
            int kk = k0 + kh*32;
            #pragma unroll
            for (int j = 0; j < 2; j++) {
                int row = lrow + j*64;
                int gm = m0 + row;
                if (rev) gm = (gm & ~(SEQ-1)) | ((SEQ-1) - (gm & (SEQ-1)));
                uint32_t d = sA + kh*8192 + row*64 + ((lkc ^ ((row>>1)&3))*16);
                cp16(d, A + (size_t)gm*lda + kk + lkc*8, 16);
            }
            #pragma unroll
            for (int j = 0; j < 2; j++) {
                int row = lrow + j*64;
                int wr = n0 + row;
                int valid = (wr < N);
                uint32_t d = sB + kh*8192 + row*64 + ((lkc ^ ((row>>1)&3))*16);
                cp16(d, W + (size_t)(valid ? wr : 0)*ldw + kk + lkc*8, valid ? 16 : 0);
            }
        }
        cp_commit();
    };

    stage_load(0);
    if (nk > 1) stage_load(1); else cp_commit();

    for (int it = 0; it < nk; it++) {
        cp_wait1();
        __syncthreads();
        if (it + 2 < nk) stage_load(it + 2); else cp_commit();

        uint32_t sb = sbase + (it % 3)*HSTG;
        #pragma unroll
        for (int ks4 = 0; ks4 < 4; ks4++) {
            const uint32_t sub = (uint32_t)(ks4 >> 1) * 8192;
            const uint32_t kx  = (uint32_t)(ks4 & 1) * 32;
            uint32_t af[4][4];
            #pragma unroll
            for (int mi = 0; mi < 4; mi++)
                LDSM4(af[mi][0], af[mi][1], af[mi][2], af[mi][3],
                      sb + sub + (aaddr[mi] ^ kx));
            uint32_t bf[4][2];
            #pragma unroll
            for (int p = 0; p < 2; p++)
                LDSM4(bf[2*p][0], bf[2*p][1], bf[2*p+1][0], bf[2*p+1][1],
                      sb + 16384 + sub + (baddr[p] ^ kx));
            #pragma unroll
            for (int mi = 0; mi < 4; mi++)
                #pragma unroll
                for (int ni = 0; ni < 4; ni++) {
                    asm volatile(
                        "mma.sync.aligned.m16n8k16.row.col.f32.f16.f16.f32 "
                        "{%0,%1,%2,%3}, {%4,%5,%6,%7}, {%8,%9}, {%0,%1,%2,%3};"
                        : "+f"(acc[mi][ni][0]), "+f"(acc[mi][ni][1]),
                          "+f"(acc[mi][ni][2]), "+f"(acc[mi][ni][3])
                        : "r"(af[mi][0]), "r"(af[mi][1]),
                          "r"(af[mi][2]), "r"(af[mi][3]),
                          "r"(bf[ni][0]), "r"(bf[ni][1]));
                }
        }
        __syncthreads();
    }

    #pragma unroll
    for (int mi = 0; mi < 4; mi++) {
        #pragma unroll
        for (int ni = 0; ni < 4; ni++) {
            int row = m0 + warp_m + mi*16 + (lane>>2);
            int col = n0 + warp_n + ni*8 + 2*(lane&3);
            #pragma unroll
            for (int half = 0; half < 2; half++) {
                int r = row + half*8;
                float v0 = acc[mi][ni][half*2+0];
                float v1 = acc[mi][ni][half*2+1];
                if (EPI == 1) {
                    v0 += bias[col];   v1 += bias[col+1];
                    v0 = (v0 > 20.f) ? v0 : log1pf(__expf(v0));
                    v1 = (v1 > 20.f) ? v1 : log1pf(__expf(v1));
                } else if (EPI == 2) {
                    v0 = 1.f / (1.f + __expf(-v0));
                    v1 = 1.f / (1.f + __expf(-v1));
                }
                if (col + 1 < N)
                    *(float2*)(C + (size_t)r*Ntot + col) = make_float2(v0, v1);
            }
        }
    }
}

// ---------------- split-K reduce for x_proj (per-dir) ------------------------
__global__ void reduce_dbc_kernel(int dirsel) {
    int idx = blockIdx.x * blockDim.x + threadIdx.x;
    const int TOT = NROWS*DBCN;
    if (idx >= TOT) return;
    int dir = dirsel;
    float s = 0.f;
    #pragma unroll
    for (int p = 0; p < NSPLIT; p++) s += g_dbcp[dir][p][idx];
    g_dbc[dir][idx] = s;
    g_dbch[dir][idx] = __float2half(s);
}

// ---------------- causal depthwise conv (k=4) + SiLU -> fp16 (per-dir) ------
__global__ void conv_silu_kernel(const float* __restrict__ w0, const float* __restrict__ w1,
                                 const float* __restrict__ cb0, const float* __restrict__ cb1,
                                 int dirsel) {
    int dir = dirsel;
    const float* w  = dir ? w1 : w0;
    const float* cb = dir ? cb1 : cb0;
    int idx = blockIdx.x * blockDim.x + threadIdx.x;
    const int NC4 = DINNER/4;
    const int NPAIR = NROWS/2;
    if (idx >= NPAIR * NC4) return;
    int c4 = idx % NC4;
    int pr = idx / NC4;
    int row0 = pr * 2;
    int l0 = row0 & (SEQ-1);
    const float* base = g_xz[dir] + (size_t)row0*XZN + c4*4;
    float4 xp1 = *(const float4*)(base + XZN);
    float4 x0  = *(const float4*)(base);
    float4 xm1 = (l0>=1) ? *(const float4*)(base - 1*XZN) : make_float4(0,0,0,0);
    float4 xm2 = (l0>=2) ? *(const float4*)(base - 2*XZN) : make_float4(0,0,0,0);
    float4 xm3 = (l0>=3) ? *(const float4*)(base - 3*XZN) : make_float4(0,0,0,0);
    float4 cbv = ((const float4*)cb)[c4];

    float o0[4], o1[4];
    const float* cbp = (const float*)&cbv;
    const float* pxp1 = (const float*)&xp1;
    const float* px0  = (const float*)&x0;
    const float* pxm1 = (const float*)&xm1;
    const float* pxm2 = (const float*)&xm2;
    const float* pxm3 = (const float*)&xm3;
    #pragma unroll
    for (int c = 0; c < 4; c++) {
        float4 wv = ((const float4*)w)[c4*4+c];
        float a = cbp[c];
        a = fmaf(wv.x, pxm3[c], a);
        a = fmaf(wv.y, pxm2[c], a);
        a = fmaf(wv.z, pxm1[c], a);
        a = fmaf(wv.w, px0[c], a);
        o0[c] = a / (1.f + __expf(-a));
        float b = cbp[c];
        b = fmaf(wv.x, pxm2[c], b);
        b = fmaf(wv.y, pxm1[c], b);
        b = fmaf(wv.z, px0[c], b);
        b = fmaf(wv.w, pxp1[c], b);
        o1[c] = b / (1.f + __expf(-b));
    }
    __half* h0 = g_xih[dir] + (size_t)row0*DINNER + c4*4;
    *(__half2*)(h0)            = __floats2half2_rn(o0[0], o0[1]);
    *(__half2*)(h0+2)          = __floats2half2_rn(o0[2], o0[3]);
    *(__half2*)(h0+DINNER)     = __floats2half2_rn(o1[0], o1[1]);
    *(__half2*)(h0+DINNER+2)   = __floats2half2_rn(o1[2], o1[3]);
}

// ---------------- chunked scan: pass A (per-dir) -----------------------------
__global__ __launch_bounds__(128)
void scan_local_kernel(const float* __restrict__ cw0, const float* __restrict__ cw1,
                       const float* __restrict__ cb0, const float* __restrict__ cb1,
                       int dirsel) {
    int dir = dirsel;
    int b   = blockIdx.z;
    int c   = blockIdx.y;                 // 0..NCHUNK-2
    int d   = blockIdx.x * 128 + threadIdx.x;
    int row0 = c * CHLEN;

    __shared__ float4 sB[CHLEN][4];
    for (int i = threadIdx.x; i < CHLEN*4; i += 128) {
        int row = i >> 2, q = i & 3;
        sB[row][q] = *(const float4*)(g_dbc[dir] +
                        (size_t)(b*SEQ + row0 + row)*DBCN + 64 + q*4);
    }
    __syncthreads();

    const float* dtp = g_dt[dir]  + ((size_t)(b*SEQ + row0))*DINNER + d;
    const float* xzp = g_xz[dir]  + ((size_t)(b*SEQ + row0))*XZN + d;
    const float* cw  = dir ? cw1 : cw0;
    const float* cb  = dir ? cb1 : cb0;

    float4 wv = ((const float4*)cw)[d];
    float cbv = cb[d];
    float x1 = 0.f, x2 = 0.f, x3 = 0.f;
    if (c > 0) {
        x1 = xzp[-(ptrdiff_t)XZN];
        x2 = xzp[-(ptrdiff_t)(2*XZN)];
        x3 = xzp[-(ptrdiff_t)(3*XZN)];
    }

    float h[DSTATE];
    #pragma unroll
    for (int s = 0; s < DSTATE; s++) h[s] = 0.f;
    float Av[DSTATE];
    #pragma unroll
    for (int s = 0; s < DSTATE; s++) Av[s] = g_A[dir][d*DSTATE + s];
    int fast = g_fastA[dir];
    float sdt = 0.f;

    #pragma unroll 1
    for (int l0 = 0; l0 < CHLEN; l0 += 4) {
        float cdt[4], cx[4];
        #pragma unroll
        for (int u = 0; u < 4; u++) {
            int r = l0 + u;
            cdt[u] = dtp[(size_t)r*DINNER];
            cx[u]  = xzp[(size_t)r*XZN];
        }
        #pragma unroll
        for (int u = 0; u < 4; u++) {
            int r = l0 + u;
            float dt = cdt[u], xc = cx[u];
            float a = cbv;
            a = fmaf(wv.x, x3, a);
            a = fmaf(wv.y, x2, a);
            a = fmaf(wv.z, x1, a);
            a = fmaf(wv.w, xc, a);
            float xi = a / (1.f + __expf(-a));
            x3 = x2; x2 = x1; x1 = xc;

            float4 b0 = sB[r][0], b1 = sB[r][1], b2 = sB[r][2], b3 = sB[r][3];
            float bsv[16] = {b0.x,b0.y,b0.z,b0.w, b1.x,b1.y,b1.z,b1.w,
                             b2.x,b2.y,b2.z,b2.w, b3.x,b3.y,b3.z,b3.w};
            float dtxi = dt * xi;
            sdt += dt;
            if (fast) {
                float e = __expf(-dt);
                float p = 1.f;
                #pragma unroll
                for (int s = 0; s < DSTATE; s++) {
                    p *= e;
                    h[s] = fmaf(p, h[s], dtxi * bsv[s]);
                }
            } else {
                #pragma unroll
                for (int s = 0; s < DSTATE; s++) {
                    float aa = __expf(dt * Av[s]);
                    h[s] = fmaf(aa, h[s], dtxi * bsv[s]);
                }
            }
        }
    }
    #pragma unroll
    for (int s = 0; s < DSTATE; s++) g_hloc[dir][b][c][s][d] = h[s];
    g_sdt[dir][b][c][d] = sdt;
}

// ---------------- chunked scan: pass C (per-dir) -----------------------------
__global__ __launch_bounds__(128)
void scan_final_kernel(const float* __restrict__ cw0, const float* __restrict__ cw1,
                       const float* __restrict__ cb0, const float* __restrict__ cb1,
                       const float* __restrict__ D0, const float* __restrict__ D1,
                       int dirsel) {
    int dir = dirsel;
    int b   = blockIdx.z;
    int c   = blockIdx.y;
    int d   = blockIdx.x * 128 + threadIdx.x;
    int row0 = c * CHLEN;
    const float* Dp = dir ? D1 : D0;

    __shared__ float4 sBC[CHLEN][8];
    for (int i = threadIdx.x; i < CHLEN*8; i += 128) {
        int row = i >> 3, q = i & 7;
        sBC[row][q] = *(const float4*)(g_dbc[dir] +
                         (size_t)(b*SEQ + row0 + row)*DBCN + 64 + q*4);
    }
    __syncthreads();

    const float* dtp = g_dt[dir]  + ((size_t)(b*SEQ + row0))*DINNER + d;
    const float* xzp = g_xz[dir]  + ((size_t)(b*SEQ + row0))*XZN + d;
    const float* zp  = g_xz[dir]  + ((size_t)(b*SEQ + row0))*XZN + DINNER + d;
    __half* yp       = g_yh[dir]  + ((size_t)(b*SEQ + row0))*DINNER + d;
    const float* cw  = dir ? cw1 : cw0;
    const float* cb  = dir ? cb1 : cb0;

    float Av[DSTATE];
    #pragma unroll
    for (int s = 0; s < DSTATE; s++) Av[s] = g_A[dir][d*DSTATE + s];
    int fast = g_fastA[dir];

    float h[DSTATE];
    #pragma unroll
    for (int s = 0; s < DSTATE; s++) h[s] = 0.f;
    for (int cc = 0; cc < c; cc++) {
        float S = g_sdt[dir][b][cc][d];
        if (fast) {
            float E = __expf(-S);
            float p = 1.f;
            #pragma unroll
            for (int s = 0; s < DSTATE; s++) {
                p *= E;
                h[s] = fmaf(p, h[s], g_hloc[dir][b][cc][s][d]);
            }
        } else {
            #pragma unroll
            for (int s = 0; s < DSTATE; s++) {
                float aa = __expf(Av[s] * S);
                h[s] = fmaf(aa, h[s], g_hloc[dir][b][cc][s][d]);
            }
        }
    }

    float4 wv = ((const float4*)cw)[d];
    float cbv = cb[d];
    float x1 = 0.f, x2 = 0.f, x3 = 0.f;
    if (c > 0) {
        x1 = xzp[-(ptrdiff_t)XZN];
        x2 = xzp[-(ptrdiff_t)(2*XZN)];
        x3 = xzp[-(ptrdiff_t)(3*XZN)];
    }
    float Dv = Dp[d];

    #pragma unroll 1
    for (int l0 = 0; l0 < CHLEN; l0 += 4) {
        float cdt[4], cx[4], cz[4];
        #pragma unroll
        for (int u = 0; u < 4; u++) {
            int r = l0 + u;
            cdt[u] = dtp[(size_t)r*DINNER];
            cx[u]  = xzp[(size_t)r*XZN];
            cz[u]  = zp [(size_t)r*XZN];
        }
        #pragma unroll
        for (int u = 0; u < 4; u++) {
            int r = l0 + u;
            float dt = cdt[u], xc = cx[u], z = cz[u];
            float a = cbv;
            a = fmaf(wv.x, x3, a);
            a = fmaf(wv.y, x2, a);
            a = fmaf(wv.z, x1, a);
            a = fmaf(wv.w, xc, a);
            float xi = a / (1.f + __expf(-a));
            x3 = x2; x2 = x1; x1 = xc;

            float4 b0 = sBC[r][0], b1 = sBC[r][1], b2 = sBC[r][2], b3 = sBC[r][3];
            float4 c0 = sBC[r][4], c1 = sBC[r][5], c2 = sBC[r][6], c3 = sBC[r][7];
            float bsv[16] = {b0.x,b0.y,b0.z,b0.w, b1.x,b1.y,b1.z,b1.w,
                             b2.x,b2.y,b2.z,b2.w, b3.x,b3.y,b3.z,b3.w};
            float csv[16] = {c0.x,c0.y,c0.z,c0.w, c1.x,c1.y,c1.z,c1.w,
                             c2.x,c2.y,c2.z,c2.w, c3.x,c3.y,c3.z,c3.w};

            float dtxi = dt * xi;
            float acc = 0.f;
            if (fast) {
                float e = __expf(-dt);
                float p = 1.f;
                #pragma unroll
                for (int s = 0; s < DSTATE; s++) {
                    p *= e;
                    h[s] = fmaf(p, h[s], dtxi * bsv[s]);
                    acc = fmaf(h[s], csv[s], acc);
                }
            } else {
                #pragma unroll
                for (int s = 0; s < DSTATE; s++) {
                    float aa = __expf(dt * Av[s]);
                    h[s] = fmaf(aa, h[s], dtxi * bsv[s]);
                    acc = fmaf(h[s], csv[s], acc);
                }
            }
            float sz = z / (1.f + __expf(-z));
            yp[(size_t)r*DINNER] = __float2half((acc + xi * Dv) * sz);
        }
    }
}

// ---------------- combine dirs + LayerNorm + residual (float4) --------------
__global__ __launch_bounds__(256)
void combine_ln_kernel(const float* __restrict__ x,
                       const float* __restrict__ lng, const float* __restrict__ lnb,
                       float* __restrict__ out) {
    int row = blockIdx.x;
    int b = row / SEQ, l = row % SEQ;
    const float* f  = g_outd[0] + (size_t)row*DMODEL;
    const float* bk = g_outd[1] + (size_t)(b*SEQ + (SEQ-1-l))*DMODEL;
    int tid = threadIdx.x;

    float4 fv = *(const float4*)(f + tid*4);
    float4 bv = *(const float4*)(bk + tid*4);
    float4 dv = make_float4(0.5f*(fv.x+bv.x), 0.5f*(fv.y+bv.y),
                            0.5f*(fv.z+bv.z), 0.5f*(fv.w+bv.w));
    float s  = dv.x + dv.y + dv.z + dv.w;
    float s2 = dv.x*dv.x + dv.y*dv.y + dv.z*dv.z + dv.w*dv.w;
    #pragma unroll
    for (int o = 16; o; o >>= 1) {
        s  += __shfl_xor_sync(0xffffffffu, s,  o);
        s2 += __shfl_xor_sync(0xffffffffu, s2, o);
    }
    __shared__ float sh[2][8];
    if ((tid & 31) == 0) { sh[0][tid>>5] = s; sh[1][tid>>5] = s2; }
    __syncthreads();
    if (tid < 32) {
        float a  = (tid < 8) ? sh[0][tid] : 0.f;
        float a2 = (tid < 8) ? sh[1][tid] : 0.f;
        #pragma unroll
        for (int o = 4; o; o >>= 1) {
            a  += __shfl_xor_sync(0xffffffffu, a,  o);
            a2 += __shfl_xor_sync(0xffffffffu, a2, o);
        }
        if (tid == 0) { sh[0][0] = a; sh[1][0] = a2; }
    }
    __syncthreads();
    float mu  = sh[0][0] * (1.f/DMODEL);
    float var = sh[1][0] * (1.f/DMODEL) - mu*mu;
    float rstd = rsqrtf(var + 1e-5f);
    float4 gv = *(const float4*)(lng + tid*4);
    float4 bb = *(const float4*)(lnb + tid*4);
    float4 xv = *(const float4*)(x + (size_t)row*DMODEL + tid*4);
    float4 ov;
    ov.x = (dv.x - mu)*rstd*gv.x + bb.x + xv.x;
    ov.y = (dv.y - mu)*rstd*gv.y + bb.y + xv.y;
    ov.z = (dv.z - mu)*rstd*gv.z + bb.z + xv.z;
    ov.w = (dv.w - mu)*rstd*gv.w + bb.w + xv.w;
    *(float4*)(out + (size_t)row*DMODEL + tid*4) = ov;
}

// ---------------- host launcher --------------------------------------------
extern "C" void kernel_launch(void* const* d_in, const int* in_sizes, int n_in,
                              void* d_out, int out_size) {
    (void)in_sizes; (void)n_in; (void)out_size;
    const float* x       = (const float*)d_in[0];
    const float* Win[2]  = {(const float*)d_in[1],  (const float*)d_in[10]};
    const float* cw[2]   = {(const float*)d_in[2],  (const float*)d_in[11]};
    const float* cbv[2]  = {(const float*)d_in[3],  (const float*)d_in[12]};
    const float* xproj[2]= {(const float*)d_in[4],  (const float*)d_in[13]};
    const float* dtw[2]  = {(const float*)d_in[5],  (const float*)d_in[14]};
    const float* dtb[2]  = {(const float*)d_in[6],  (const float*)d_in[15]};
    const float* Alog[2] = {(const float*)d_in[7],  (const float*)d_in[16]};
    const float* Dp[2]   = {(const float*)d_in[8],  (const float*)d_in[17]};
    const float* Wout[2] = {(const float*)d_in[9],  (const float*)d_in[18]};
    const float* lng = (const float*)d_in[19];
    const float* lnb = (const float*)d_in[20];
    float* out = (float*)d_out;

    float *p_xz, *p_dbcp, *p_dt, *p_out;
    cudaGetSymbolAddress((void**)&p_xz,   g_xz);
    cudaGetSymbolAddress((void**)&p_dbcp, g_dbcp);
    cudaGetSymbolAddress((void**)&p_dt,   g_dt);
    cudaGetSymbolAddress((void**)&p_out,  g_outd);
    __half *p_xh, *p_winh, *p_xih, *p_xprojh, *p_dbch, *p_dtwh, *p_yh, *p_wouth;
    cudaGetSymbolAddress((void**)&p_xh,     g_xh);
    cudaGetSymbolAddress((void**)&p_winh,   g_winh);
    cudaGetSymbolAddress((void**)&p_xih,    g_xih);
    cudaGetSymbolAddress((void**)&p_xprojh, g_xprojh);
    cudaGetSymbolAddress((void**)&p_dbch,   g_dbch);
    cudaGetSymbolAddress((void**)&p_dtwh,   g_dtwh);
    cudaGetSymbolAddress((void**)&p_yh,     g_yh);
    cudaGetSymbolAddress((void**)&p_wouth,  g_wouth);

    const size_t sXZ  = (size_t)NROWS*XZN;
    const size_t sIN  = (size_t)NROWS*DINNER;
    const size_t sDBC = (size_t)NROWS*DBCN;
    const size_t sMD  = (size_t)NROWS*DMODEL;
    const int SMEM = 3*HSTG;   // 98304

    cudaFuncSetAttribute(hgemm<0>, cudaFuncAttributeMaxDynamicSharedMemorySize, SMEM);
    cudaFuncSetAttribute(hgemm<1>, cudaFuncAttributeMaxDynamicSharedMemorySize, SMEM);
    cudaFuncSetAttribute(hgemm<2>, cudaFuncAttributeMaxDynamicSharedMemorySize, SMEM);

    cudaStream_t s1;
    cudaEvent_t evF, evP, evJ;
    cudaStreamCreateWithFlags(&s1, cudaStreamNonBlocking);
    cudaEventCreateWithFlags(&evF, cudaEventDisableTiming);
    cudaEventCreateWithFlags(&evP, cudaEventDisableTiming);
    cudaEventCreateWithFlags(&evJ, cudaEventDisableTiming);

    // fork immediately: prepA runs on s1 concurrently with f2h on stream 0
    cudaEventRecord(evF, 0);
    cudaStreamWaitEvent(s1, evF, 0);
    prepA_kernel<<<2, 256, 0, s1>>>(Alog[0], Alog[1]);

    {
        CvtSegs cs;
        const float* srcs[9] = {x, Win[0], Win[1], xproj[0], xproj[1],
                                dtw[0], dtw[1], Wout[0], Wout[1]};
        __half* dsts[9] = {p_xh, p_winh, p_winh + (size_t)XZN*DMODEL,
                           p_xprojh, p_xprojh + (size_t)DBCN*DINNER,
                           p_dtwh, p_dtwh + (size_t)DINNER*64,
                           p_wouth, p_wouth + (size_t)DMODEL*DINNER};
        int cnts[9] = {NROWS*DMODEL, XZN*DMODEL, XZN*DMODEL,
                       DBCN*DINNER, DBCN*DINNER, DINNER*64, DINNER*64,
                       DMODEL*DINNER, DMODEL*DINNER};
        int off = 0;
        for (int i = 0; i < 9; i++) { cs.s[i]=srcs[i]; cs.d[i]=dsts[i]; cs.off[i]=off; off+=cnts[i]; }
        cs.off[9] = off;
        f2h_multi_kernel<<<(off/4 + 255)/256, 256>>>(cs);
    }

    // stream 0's dir0 chain must also see f2h; s1 must see f2h (via event) and
    // already has prepA ordered. Record f2h completion for s1.
    cudaEventRecord(evP, 0);
    cudaStreamWaitEvent(s1, evP, 0);
    // stream 0 must see prepA (needed by scans); prepA is tiny and finishes
    // under f2h, but order it explicitly:
    cudaEventRecord(evF, s1);            // after prepA on s1
    cudaStreamWaitEvent((cudaStream_t)0, evF, 0);

    for (int dir = 0; dir < 2; dir++) {
        cudaStream_t st = dir ? s1 : (cudaStream_t)0;

        hgemm<0><<<dim3(XZN/128, NROWS/128, 1), 256, SMEM, st>>>(
            p_xh, p_xh, p_winh, p_winh + (size_t)XZN*DMODEL, nullptr, nullptr,
            p_xz, p_xz + sXZ, XZN, XZN, DMODEL, DMODEL, DMODEL, 0, 1, dir);

        conv_silu_kernel<<<dim3(((NROWS/2)*(DINNER/4) + 255)/256, 1, 1), 256, 0, st>>>(
            cw[0], cw[1], cbv[0], cbv[1], dir);

        hgemm<0><<<dim3(1, NROWS/128, NSPLIT), 256, SMEM, st>>>(
            p_xih, p_xih + sIN, p_xprojh, p_xprojh + (size_t)DBCN*DINNER,
            nullptr, nullptr,
            p_dbcp, p_dbcp + NSPLIT*sDBC, DBCN, DBCN, DINNER/NSPLIT, DINNER, DINNER,
            sDBC, 0, dir);
        reduce_dbc_kernel<<<(NROWS*DBCN + 255)/256, 256, 0, st>>>(dir);

        hgemm<1><<<dim3(DINNER/128, NROWS/128, 1), 256, SMEM, st>>>(
            p_dbch, p_dbch + sDBC, p_dtwh, p_dtwh + (size_t)DINNER*64, dtb[0], dtb[1],
            p_dt, p_dt + sIN, DINNER, DINNER, 64, DBCN, 64, 0, 0, dir);

        scan_local_kernel<<<dim3(DINNER/128, NCHUNK-1, BATCH), 128, 0, st>>>(
            cw[0], cw[1], cbv[0], cbv[1], dir);
        scan_final_kernel<<<dim3(DINNER/128, NCHUNK, BATCH), 128, 0, st>>>(
            cw[0], cw[1], cbv[0], cbv[1], Dp[0], Dp[1], dir);

        hgemm<2><<<dim3(DMODEL/128, NROWS/128, 1), 256, SMEM, st>>>(
            p_yh, p_yh + sIN, p_wouth, p_wouth + (size_t)DMODEL*DINNER,
            nullptr, nullptr,
            p_out, p_out + sMD, DMODEL, DMODEL, DINNER, DINNER, DINNER, 0, 0, dir);
    }

    cudaEventRecord(evJ, s1);
    cudaStreamWaitEvent((cudaStream_t)0, evJ, 0);
    combine_ln_kernel<<<NROWS, 256>>>(x, lng, lnb, out);
}